// round 14
// baseline (speedup 1.0000x reference)
#include <cuda_runtime.h>
#include <cuda_bf16.h>
#include <cstdint>

// ===========================================================================
// RouteNTMMatrix: bf16 mma.sync + ldmatrix; FOUR independent 128-thread
// pipelines per CTA; 32-row tiles; warp = m32 x n32; single barrier/tile
// (oac 2-slot, rv5/tv5 3-slot rotation).
// ===========================================================================

#define DIM    256
#define KOUT   100
#define CDIM   5
#define XSTR   132            // row stride in uint32 (bf16x2); 132%32=4 -> LDSM conflict-free

// word offsets in dynamic smem
#define WP_W   0                            // w bf16-pairs [128n][132]
#define XB_W   (WP_W + 128 * XSTR)          // x tiles: 4 groups x 2 slots x [32][132]
#define FCS_W  (XB_W + 8 * 32 * XSTR)
#define FCI_W  (FCS_W + 128)
#define BIA_W  (FCI_W + 32)
#define OAC_W  (BIA_W + 32)                 // 4 groups x 2 slots x 32
#define RV5_W  (OAC_W + 256)                // 4 groups x 3 slots x 32 x 5
#define TV5_W  (RV5_W + 4 * 3 * 32 * CDIM)
#define SM_WORDS (TV5_W + 4 * 3 * 32 * CDIM)   // 54976 words = 219904 B

__device__ float g_ra[100000 * CDIM];
__device__ float g_tb[2048   * CDIM];
__device__ __nv_bfloat16 g_rtb[100000 * DIM];
__device__ __nv_bfloat16 g_ttb[2048   * DIM];

__device__ __forceinline__ uint32_t pack_bf16(float lo, float hi) {
    uint32_t u;
    asm("cvt.rn.bf16x2.f32 %0, %1, %2;" : "=r"(u) : "f"(hi), "f"(lo));
    return u;
}
__device__ __forceinline__ void mma_bf16(float* d, const uint32_t* a,
                                         uint32_t b0, uint32_t b1) {
    asm volatile("mma.sync.aligned.m16n8k16.row.col.f32.bf16.bf16.f32 "
                 "{%0,%1,%2,%3}, {%4,%5,%6,%7}, {%8,%9}, {%0,%1,%2,%3};"
                 : "+f"(d[0]), "+f"(d[1]), "+f"(d[2]), "+f"(d[3])
                 : "r"(a[0]), "r"(a[1]), "r"(a[2]), "r"(a[3]), "r"(b0), "r"(b1));
}
#define LDSM_X4(r0, r1, r2, r3, addr) \
    asm volatile("ldmatrix.sync.aligned.m8n8.x4.shared.b16 {%0,%1,%2,%3}, [%4];" \
                 : "=r"(r0), "=r"(r1), "=r"(r2), "=r"(r3) : "r"(addr))
#define BARG(id) asm volatile("bar.sync %0, %1;" :: "r"(id), "r"(128) : "memory")

__device__ __forceinline__ uint32_t smem_u32(const void* p) {
    uint32_t a;
    asm("{ .reg .u64 t; cvta.to.shared.u64 t, %1; cvt.u32.u64 %0, t; }" : "=r"(a) : "l"(p));
    return a;
}
__device__ __forceinline__ uint4 hmul8(uint4 a, uint4 b) {
    const __nv_bfloat162* pa = reinterpret_cast<const __nv_bfloat162*>(&a);
    const __nv_bfloat162* pb = reinterpret_cast<const __nv_bfloat162*>(&b);
    __nv_bfloat162 x0 = __hmul2(pa[0], pb[0]);
    __nv_bfloat162 x1 = __hmul2(pa[1], pb[1]);
    __nv_bfloat162 x2 = __hmul2(pa[2], pb[2]);
    __nv_bfloat162 x3 = __hmul2(pa[3], pb[3]);
    uint4 r;
    r.x = *reinterpret_cast<uint32_t*>(&x0);
    r.y = *reinterpret_cast<uint32_t*>(&x1);
    r.z = *reinterpret_cast<uint32_t*>(&x2);
    r.w = *reinterpret_cast<uint32_t*>(&x3);
    return r;
}

// ---------------------------------------------------------------------------
// proj + convert: warp per 8 rows (16 LDG.128 batched -> high MLP).
// Pt layout: [c][h][j][lane].
// ---------------------------------------------------------------------------
__global__ __launch_bounds__(512)
void proj_conv(const float* __restrict__ route_table,
               const float* __restrict__ time_table,
               const float* __restrict__ mode_a,
               const float* __restrict__ mode_b,
               float* __restrict__ ra_tab, float* __restrict__ tb_tab,
               __nv_bfloat16* __restrict__ rtb, __nv_bfloat16* __restrict__ ttb,
               int n_routes, int n_time)
{
    __shared__ float PtA[CDIM * 2 * 4 * 32];
    __shared__ float PtB[CDIM * 2 * 4 * 32];
    const int tid = threadIdx.x;
    for (int i = tid; i < CDIM * 2 * 4 * 32; i += 512) {
        const int ln = i & 31, j = (i >> 5) & 3, h = (i >> 7) & 1, c = i >> 8;
        const int d = h * 128 + 4 * ln + j;
        PtA[i] = __ldg(mode_a + d * CDIM + c);
        PtB[i] = __ldg(mode_b + d * CDIM + c);
    }
    __syncthreads();

    const int lane  = tid & 31;
    const int total = n_routes + n_time;
    const int base  = (blockIdx.x * 16 + (tid >> 5)) * 8;
    if (base >= total) return;

    float4 va[8][2];
    int   rws[8];
    bool  isr[8];
#pragma unroll
    for (int jr = 0; jr < 8; jr++) {
        const int row = min(base + jr, total - 1);
        rws[jr] = row;
        isr[jr] = row < n_routes;
        const float* rf = (isr[jr] ? route_table : time_table)
                          + (size_t)(isr[jr] ? row : row - n_routes) * DIM;
        const float4* p = reinterpret_cast<const float4*>(rf);
        va[jr][0] = __ldg(p + lane);
        va[jr][1] = __ldg(p + 32 + lane);
    }

#pragma unroll
    for (int jr = 0; jr < 8; jr++) {
        if (jr > 0 && base + jr >= total) break;
        const bool is_r = isr[jr];
        const int  lrow = is_r ? rws[jr] : rws[jr] - n_routes;
        const float4 v0 = va[jr][0], v1 = va[jr][1];
        const float* Pt = is_r ? PtA : PtB;

        uint2* brow = reinterpret_cast<uint2*>((is_r ? rtb : ttb) + (size_t)lrow * DIM);
        brow[lane]      = make_uint2(pack_bf16(v0.x, v0.y), pack_bf16(v0.z, v0.w));
        brow[lane + 32] = make_uint2(pack_bf16(v1.x, v1.y), pack_bf16(v1.z, v1.w));

        const float vv[2][4] = {{v0.x, v0.y, v0.z, v0.w}, {v1.x, v1.y, v1.z, v1.w}};
        float acc[CDIM] = {0.f, 0.f, 0.f, 0.f, 0.f};
#pragma unroll
        for (int c = 0; c < CDIM; c++)
#pragma unroll
            for (int h = 0; h < 2; h++)
#pragma unroll
                for (int j = 0; j < 4; j++)
                    acc[c] = fmaf(vv[h][j], Pt[((c * 2 + h) * 4 + j) * 32 + lane], acc[c]);

#pragma unroll
        for (int off = 16; off; off >>= 1)
#pragma unroll
            for (int c = 0; c < CDIM; c++) acc[c] += __shfl_xor_sync(0xffffffffu, acc[c], off);

        if (lane == 0) {
            float* o = (is_r ? ra_tab : tb_tab) + (size_t)lrow * CDIM;
#pragma unroll
            for (int c = 0; c < CDIM; c++) o[c] = acc[c];
        }
    }
}

// ---------------------------------------------------------------------------
// Main persistent kernel: 512 threads = 4 independent 128-thread groups.
// Group tile = 32 rows; warp nq covers cols nq*32, full m32 (2 x m16).
// ---------------------------------------------------------------------------
__global__ __launch_bounds__(512, 1)
void main_kernel(const int*   __restrict__ route_idx,
                 const int*   __restrict__ time_idx,
                 const uint4* __restrict__ RTB,
                 const uint4* __restrict__ TTB,
                 const float* __restrict__ w,
                 const float* __restrict__ fc_w,
                 const float* __restrict__ fc_b,
                 const float* __restrict__ mode_bias,
                 const float* __restrict__ ra_tab,
                 const float* __restrict__ tb_tab,
                 float*       __restrict__ out,
                 int batch, int ntiles)
{
    extern __shared__ uint32_t smu[];
    uint32_t* wp  = smu + WP_W;
    float*    fcs = reinterpret_cast<float*>(smu + FCS_W);
    float*    fci = reinterpret_cast<float*>(smu + FCI_W);
    float*    bia = reinterpret_cast<float*>(smu + BIA_W);

    const int tid  = threadIdx.x;
    const int gid  = tid >> 7;            // group 0..3
    const int lt   = tid & 127;
    const int lw   = lt >> 5;             // warp in group 0..3 (= nq)
    const int lane = tid & 31;
    const uint32_t sm_u32 = smem_u32(smu);

    // stage w bf16-pairs (all 512 threads)
    for (int i = tid; i < 128 * 128; i += 512) {
        const int n = i & 127, kp = i >> 7;
        const float f0 = (n < KOUT) ? __ldg(w + (2 * kp)     * KOUT + n) : 0.f;
        const float f1 = (n < KOUT) ? __ldg(w + (2 * kp + 1) * KOUT + n) : 0.f;
        wp[n * XSTR + kp] = pack_bf16(f0, f1);
    }
    if (tid < 128)                 fcs[tid] = (tid < KOUT) ? __ldg(fc_w + tid) : 0.f;
    if (tid >= 128 && tid < 153)   fci[tid - 128] = __ldg(fc_w + KOUT + tid - 128);
    if (tid >= 160 && tid < 185)   bia[tid - 160] = __ldg(mode_bias + tid - 160);
    if (tid < 256)                 reinterpret_cast<float*>(smu + OAC_W)[tid] = 0.f;

    const float fcb = __ldg(fc_b);

    float*    oacg = reinterpret_cast<float*>(smu + OAC_W) + gid * 64;
    uint32_t* xg   = smu + XB_W + gid * (2 * 32 * XSTR);
    float*    rv5g = reinterpret_cast<float*>(smu + RV5_W) + gid * (3 * 32 * CDIM);
    float*    tv5g = reinterpret_cast<float*>(smu + TV5_W) + gid * (3 * 32 * CDIM);

    const int nq = lw;                    // n-quarter
    const int t  = lane & 3;
    const int barid = 1 + gid;

    // ldmatrix addressing
    const int a_row = (lane & 7) + ((lane >> 3) & 1) * 8;
    const int a_kq  = (lane >> 4) * 4;
    const int b_n   = ((lane >> 4) << 3) + (lane & 7);
    const int b_kq  = ((lane >> 3) & 1) * 4;
    uint32_t bAddr[2];
#pragma unroll
    for (int p = 0; p < 2; p++)
        bAddr[p] = sm_u32 + (WP_W + (nq * 32 + p * 16 + b_n) * XSTR + b_kq) * 4;

    const int step  = gridDim.x * 4;
    const int first = blockIdx.x * 4 + gid;
    const int li    = lane & 7;

    __syncthreads();   // staging visible to all groups

    // ---- prologue: gather first tile -> x slot 0, rv5 slot 0 ----
    {
        const int ei = min(first * 32 + lw * 8 + li, batch - 1);
        const int ridx = __ldg(route_idx + ei);
        const int tidx = __ldg(time_idx  + ei);
        if (lane < 8) {
#pragma unroll
            for (int c = 0; c < CDIM; c++) {
                rv5g[(lw * 8 + li) * CDIM + c] = __ldg(ra_tab + (size_t)ridx * CDIM + c);
                tv5g[(lw * 8 + li) * CDIM + c] = __ldg(tb_tab + (size_t)tidx * CDIM + c);
            }
        }
#pragma unroll
        for (int h = 0; h < 2; h++) {
            uint4 rr[4], tt[4];
#pragma unroll
            for (int i = 0; i < 4; i++) {
                const int r0 = __shfl_sync(0xffffffffu, ridx, h * 4 + i);
                const int t0 = __shfl_sync(0xffffffffu, tidx, h * 4 + i);
                rr[i] = __ldg(RTB + (size_t)r0 * 32 + lane);
                tt[i] = __ldg(TTB + (size_t)t0 * 32 + lane);
            }
#pragma unroll
            for (int i = 0; i < 4; i++)
                *reinterpret_cast<uint4*>(xg + (lw * 8 + h * 4 + i) * XSTR + 4 * lane)
                    = hmul8(rr[i], tt[i]);
        }
    }
    BARG(barid);

    int it = 0;
    for (int tile = first; tile < ntiles; tile += step, it++) {
        const int s   = it & 1;
        const int rs  = it % 3;
        const int rsn = (it + 1) % 3;
        uint32_t* xb_cur = xg + s * (32 * XSTR);
        uint32_t* xb_nxt = xg + (s ^ 1) * (32 * XSTR);
        const bool have_next = (tile + step < ntiles);

        int nridx = 0, ntidx = 0;
        uint4 rr[4], tt[4];

        // ---- issue next-tile idx + rows 0-3 + rv5 prefetch (slot rsn) ----
        if (have_next) {
            const int ei = min((tile + step) * 32 + lw * 8 + li, batch - 1);
            nridx = __ldg(route_idx + ei);
            ntidx = __ldg(time_idx  + ei);
#pragma unroll
            for (int i = 0; i < 4; i++) {
                const int r0 = __shfl_sync(0xffffffffu, nridx, i);
                const int t0 = __shfl_sync(0xffffffffu, ntidx, i);
                rr[i] = __ldg(RTB + (size_t)r0 * 32 + lane);
                tt[i] = __ldg(TTB + (size_t)t0 * 32 + lane);
            }
            if (lane < 8) {
#pragma unroll
                for (int c = 0; c < CDIM; c++) {
                    rv5g[(rsn * 32 + lw * 8 + li) * CDIM + c] = __ldg(ra_tab + (size_t)nridx * CDIM + c);
                    tv5g[(rsn * 32 + lw * 8 + li) * CDIM + c] = __ldg(tb_tab + (size_t)ntidx * CDIM + c);
                }
            }
        }

        // ---- mma over K: 16 chunks of k16 ----
        float acc[2][4][4];
#pragma unroll
        for (int m = 0; m < 2; m++)
#pragma unroll
            for (int n = 0; n < 4; n++)
#pragma unroll
                for (int q = 0; q < 4; q++) acc[m][n][q] = 0.f;

        uint32_t aAddr[2];
#pragma unroll
        for (int m = 0; m < 2; m++)
            aAddr[m] = sm_u32 + (uint32_t)((xb_cur - smu)
                       + (m * 16 + a_row) * XSTR + a_kq) * 4;

        // ---- MMA kc 0-7 (hides next-tile LDG latency) ----
#pragma unroll 2
        for (int kc = 0; kc < 8; kc++) {
            const uint32_t kb = kc * 32;
            uint32_t bb[8];
            LDSM_X4(bb[0], bb[1], bb[2], bb[3], bAddr[0] + kb);
            LDSM_X4(bb[4], bb[5], bb[6], bb[7], bAddr[1] + kb);
#pragma unroll
            for (int m = 0; m < 2; m++) {
                uint32_t a[4];
                LDSM_X4(a[0], a[1], a[2], a[3], aAddr[m] + kb);
                mma_bf16(acc[m][0], a, bb[0], bb[1]);
                mma_bf16(acc[m][1], a, bb[2], bb[3]);
                mma_bf16(acc[m][2], a, bb[4], bb[5]);
                mma_bf16(acc[m][3], a, bb[6], bb[7]);
            }
        }

        // ---- commit rows 0-3; issue rows 4-7 ----
        if (have_next) {
#pragma unroll
            for (int i = 0; i < 4; i++)
                *reinterpret_cast<uint4*>(xb_nxt + (lw * 8 + i) * XSTR + 4 * lane)
                    = hmul8(rr[i], tt[i]);
#pragma unroll
            for (int i = 0; i < 4; i++) {
                const int r0 = __shfl_sync(0xffffffffu, nridx, 4 + i);
                const int t0 = __shfl_sync(0xffffffffu, ntidx, 4 + i);
                rr[i] = __ldg(RTB + (size_t)r0 * 32 + lane);
                tt[i] = __ldg(TTB + (size_t)t0 * 32 + lane);
            }
        }

        // ---- MMA kc 8-15 ----
#pragma unroll 2
        for (int kc = 8; kc < 16; kc++) {
            const uint32_t kb = kc * 32;
            uint32_t bb[8];
            LDSM_X4(bb[0], bb[1], bb[2], bb[3], bAddr[0] + kb);
            LDSM_X4(bb[4], bb[5], bb[6], bb[7], bAddr[1] + kb);
#pragma unroll
            for (int m = 0; m < 2; m++) {
                uint32_t a[4];
                LDSM_X4(a[0], a[1], a[2], a[3], aAddr[m] + kb);
                mma_bf16(acc[m][0], a, bb[0], bb[1]);
                mma_bf16(acc[m][1], a, bb[2], bb[3]);
                mma_bf16(acc[m][2], a, bb[4], bb[5]);
                mma_bf16(acc[m][3], a, bb[6], bb[7]);
            }
        }

        // ---- commit rows 4-7 ----
        if (have_next) {
#pragma unroll
            for (int i = 0; i < 4; i++)
                *reinterpret_cast<uint4*>(xb_nxt + (lw * 8 + 4 + i) * XSTR + 4 * lane)
                    = hmul8(rr[i], tt[i]);
        }

        // ---- fold relu * fc_w -> per-row partials (oac slot s) ----
        float* oacs = oacg + s * 32;
#pragma unroll
        for (int m = 0; m < 2; m++) {
            float p0 = 0.f, p1 = 0.f;
#pragma unroll
            for (int n = 0; n < 4; n++) {
                const int col = nq * 32 + n * 8 + 2 * t;
                const float f0 = fcs[col], f1 = fcs[col + 1];
                p0 = fmaf(f0, fmaxf(acc[m][n][0], 0.f), p0);
                p0 = fmaf(f1, fmaxf(acc[m][n][1], 0.f), p0);
                p1 = fmaf(f0, fmaxf(acc[m][n][2], 0.f), p1);
                p1 = fmaf(f1, fmaxf(acc[m][n][3], 0.f), p1);
            }
            p0 += __shfl_xor_sync(0xffffffffu, p0, 1);
            p0 += __shfl_xor_sync(0xffffffffu, p0, 2);
            p1 += __shfl_xor_sync(0xffffffffu, p1, 1);
            p1 += __shfl_xor_sync(0xffffffffu, p1, 2);
            if (t == 0) {
                const int row = m * 16 + (lane >> 2);
                atomicAdd(oacs + row, p0);
                atomicAdd(oacs + row + 8, p1);
            }
        }
        BARG(barid);   // single barrier: partials + slot^1 x-stores + rv5[rsn] complete

        // ---- epilogue: 4 threads/row over 32 rows ----
        {
            const int row = lt >> 2;
            const int p   = lt & 3;
            const int eo  = tile * 32 + row;
            const float* rv = rv5g + (rs * 32 + row) * CDIM;
            const float* tv = tv5g + (rs * 32 + row) * CDIM;
            const int start = p ? (1 + p * 6) : 0;
            const int cnt   = p ? 6 : 7;
            float val = 0.f;
#pragma unroll
            for (int k = 0; k < 7; k++) {
                if (k < cnt) {
                    const int idx = start + k;
                    const int i5  = idx / 5, j5 = idx - 5 * i5;
                    const float x  = fmaf(rv[i5], tv[j5], bia[idx]);
                    const float sg = 1.0f / (1.0f + __expf(-x));
                    val = fmaf(fci[idx], sg, val);
                }
            }
            val += __shfl_xor_sync(0xffffffffu, val, 1);
            val += __shfl_xor_sync(0xffffffffu, val, 2);
            if (p == 0) {
                if (eo < batch) out[eo] = fcb + oacs[row] + val;
                oacs[row] = 0.f;
            }
        }
        // next iter uses x slot s^1 / oac slot s^1 / rv5 slot rsn;
        // slot-s reuse is fenced by the next iteration's BARG.
    }
}

// ---------------------------------------------------------------------------
extern "C" void kernel_launch(void* const* d_in, const int* in_sizes, int n_in,
                              void* d_out, int out_size)
{
    const int*   route_idx   = (const int*)  d_in[0];
    const int*   time_idx    = (const int*)  d_in[1];
    const float* route_table = (const float*)d_in[2];
    const float* time_table  = (const float*)d_in[3];
    const float* w           = (const float*)d_in[4];
    const float* mode_a      = (const float*)d_in[5];
    const float* mode_b      = (const float*)d_in[6];
    const float* mode_bias   = (const float*)d_in[7];
    const float* fc_w        = (const float*)d_in[8];
    const float* fc_b        = (const float*)d_in[9];
    float*       out         = (float*)d_out;

    const int batch    = in_sizes[0];
    const int n_routes = in_sizes[2] / DIM;
    const int n_time   = in_sizes[3] / DIM;

    float *ra_ptr = nullptr, *tb_ptr = nullptr;
    __nv_bfloat16 *rtb_ptr = nullptr, *ttb_ptr = nullptr;
    cudaGetSymbolAddress((void**)&ra_ptr,  g_ra);
    cudaGetSymbolAddress((void**)&tb_ptr,  g_tb);
    cudaGetSymbolAddress((void**)&rtb_ptr, g_rtb);
    cudaGetSymbolAddress((void**)&ttb_ptr, g_ttb);

    {
        const int total = n_routes + n_time;
        proj_conv<<<(total + 127) / 128, 512>>>(route_table, time_table, mode_a, mode_b,
                                                ra_ptr, tb_ptr, rtb_ptr, ttb_ptr,
                                                n_routes, n_time);
    }

    const int ntiles = (batch + 31) / 32;
    const int smem_bytes = SM_WORDS * 4;   // 219904
    cudaFuncSetAttribute(main_kernel, cudaFuncAttributeMaxDynamicSharedMemorySize, smem_bytes);

    int grid = 148;
    main_kernel<<<grid, 512, smem_bytes>>>(route_idx, time_idx,
                                           (const uint4*)rtb_ptr, (const uint4*)ttb_ptr,
                                           w, fc_w, fc_b, mode_bias,
                                           ra_ptr, tb_ptr, out, batch, ntiles);
}

// round 15
// speedup vs baseline: 1.0612x; 1.0612x over previous
#include <cuda_runtime.h>
#include <cuda_bf16.h>
#include <cstdint>

// ===========================================================================
// RouteNTMMatrix: bf16 mma.sync + ldmatrix; FOUR independent 128-thread
// pipelines per CTA (R14 main) + 4-row/warp proj (R13).
// ===========================================================================

#define DIM    256
#define KOUT   100
#define CDIM   5
#define XSTR   132            // row stride in uint32 (bf16x2); 132%32=4 -> LDSM conflict-free

// word offsets in dynamic smem
#define WP_W   0                            // w bf16-pairs [128n][132]
#define XB_W   (WP_W + 128 * XSTR)          // x tiles: 4 groups x 2 slots x [32][132]
#define FCS_W  (XB_W + 8 * 32 * XSTR)
#define FCI_W  (FCS_W + 128)
#define BIA_W  (FCI_W + 32)
#define OAC_W  (BIA_W + 32)                 // 4 groups x 2 slots x 32
#define RV5_W  (OAC_W + 256)                // 4 groups x 3 slots x 32 x 5
#define TV5_W  (RV5_W + 4 * 3 * 32 * CDIM)
#define SM_WORDS (TV5_W + 4 * 3 * 32 * CDIM)   // 54976 words = 219904 B

__device__ float g_ra[100000 * CDIM];
__device__ float g_tb[2048   * CDIM];
__device__ __nv_bfloat16 g_rtb[100000 * DIM];
__device__ __nv_bfloat16 g_ttb[2048   * DIM];

__device__ __forceinline__ uint32_t pack_bf16(float lo, float hi) {
    uint32_t u;
    asm("cvt.rn.bf16x2.f32 %0, %1, %2;" : "=r"(u) : "f"(hi), "f"(lo));
    return u;
}
__device__ __forceinline__ void mma_bf16(float* d, const uint32_t* a,
                                         uint32_t b0, uint32_t b1) {
    asm volatile("mma.sync.aligned.m16n8k16.row.col.f32.bf16.bf16.f32 "
                 "{%0,%1,%2,%3}, {%4,%5,%6,%7}, {%8,%9}, {%0,%1,%2,%3};"
                 : "+f"(d[0]), "+f"(d[1]), "+f"(d[2]), "+f"(d[3])
                 : "r"(a[0]), "r"(a[1]), "r"(a[2]), "r"(a[3]), "r"(b0), "r"(b1));
}
#define LDSM_X4(r0, r1, r2, r3, addr) \
    asm volatile("ldmatrix.sync.aligned.m8n8.x4.shared.b16 {%0,%1,%2,%3}, [%4];" \
                 : "=r"(r0), "=r"(r1), "=r"(r2), "=r"(r3) : "r"(addr))
#define BARG(id) asm volatile("bar.sync %0, %1;" :: "r"(id), "r"(128) : "memory")

__device__ __forceinline__ uint32_t smem_u32(const void* p) {
    uint32_t a;
    asm("{ .reg .u64 t; cvta.to.shared.u64 t, %1; cvt.u32.u64 %0, t; }" : "=r"(a) : "l"(p));
    return a;
}
__device__ __forceinline__ uint4 hmul8(uint4 a, uint4 b) {
    const __nv_bfloat162* pa = reinterpret_cast<const __nv_bfloat162*>(&a);
    const __nv_bfloat162* pb = reinterpret_cast<const __nv_bfloat162*>(&b);
    __nv_bfloat162 x0 = __hmul2(pa[0], pb[0]);
    __nv_bfloat162 x1 = __hmul2(pa[1], pb[1]);
    __nv_bfloat162 x2 = __hmul2(pa[2], pb[2]);
    __nv_bfloat162 x3 = __hmul2(pa[3], pb[3]);
    uint4 r;
    r.x = *reinterpret_cast<uint32_t*>(&x0);
    r.y = *reinterpret_cast<uint32_t*>(&x1);
    r.z = *reinterpret_cast<uint32_t*>(&x2);
    r.w = *reinterpret_cast<uint32_t*>(&x3);
    return r;
}

// ---------------------------------------------------------------------------
// proj + convert (R13 variant): warp per 4 rows (8 LDG.128 in flight).
// Pt layout: [c][h][j][lane].
// ---------------------------------------------------------------------------
__global__ __launch_bounds__(512)
void proj_conv(const float* __restrict__ route_table,
               const float* __restrict__ time_table,
               const float* __restrict__ mode_a,
               const float* __restrict__ mode_b,
               float* __restrict__ ra_tab, float* __restrict__ tb_tab,
               __nv_bfloat16* __restrict__ rtb, __nv_bfloat16* __restrict__ ttb,
               int n_routes, int n_time)
{
    __shared__ float PtA[CDIM * 2 * 4 * 32];
    __shared__ float PtB[CDIM * 2 * 4 * 32];
    const int tid = threadIdx.x;
    for (int i = tid; i < CDIM * 2 * 4 * 32; i += 512) {
        const int ln = i & 31, j = (i >> 5) & 3, h = (i >> 7) & 1, c = i >> 8;
        const int d = h * 128 + 4 * ln + j;
        PtA[i] = __ldg(mode_a + d * CDIM + c);
        PtB[i] = __ldg(mode_b + d * CDIM + c);
    }
    __syncthreads();

    const int lane  = tid & 31;
    const int total = n_routes + n_time;
    const int base  = (blockIdx.x * 16 + (tid >> 5)) * 4;
    if (base >= total) return;

    float4 va[4][2];
    int   rws[4];
    bool  isr[4];
#pragma unroll
    for (int jr = 0; jr < 4; jr++) {
        const int row = min(base + jr, total - 1);
        rws[jr] = row;
        isr[jr] = row < n_routes;
        const float* rf = (isr[jr] ? route_table : time_table)
                          + (size_t)(isr[jr] ? row : row - n_routes) * DIM;
        const float4* p = reinterpret_cast<const float4*>(rf);
        va[jr][0] = __ldg(p + lane);
        va[jr][1] = __ldg(p + 32 + lane);
    }

#pragma unroll
    for (int jr = 0; jr < 4; jr++) {
        if (jr > 0 && base + jr >= total) break;
        const bool is_r = isr[jr];
        const int  lrow = is_r ? rws[jr] : rws[jr] - n_routes;
        const float4 v0 = va[jr][0], v1 = va[jr][1];
        const float* Pt = is_r ? PtA : PtB;

        uint2* brow = reinterpret_cast<uint2*>((is_r ? rtb : ttb) + (size_t)lrow * DIM);
        brow[lane]      = make_uint2(pack_bf16(v0.x, v0.y), pack_bf16(v0.z, v0.w));
        brow[lane + 32] = make_uint2(pack_bf16(v1.x, v1.y), pack_bf16(v1.z, v1.w));

        const float vv[2][4] = {{v0.x, v0.y, v0.z, v0.w}, {v1.x, v1.y, v1.z, v1.w}};
        float acc[CDIM] = {0.f, 0.f, 0.f, 0.f, 0.f};
#pragma unroll
        for (int c = 0; c < CDIM; c++)
#pragma unroll
            for (int h = 0; h < 2; h++)
#pragma unroll
                for (int j = 0; j < 4; j++)
                    acc[c] = fmaf(vv[h][j], Pt[((c * 2 + h) * 4 + j) * 32 + lane], acc[c]);

#pragma unroll
        for (int off = 16; off; off >>= 1)
#pragma unroll
            for (int c = 0; c < CDIM; c++) acc[c] += __shfl_xor_sync(0xffffffffu, acc[c], off);

        if (lane == 0) {
            float* o = (is_r ? ra_tab : tb_tab) + (size_t)lrow * CDIM;
#pragma unroll
            for (int c = 0; c < CDIM; c++) o[c] = acc[c];
        }
    }
}

// ---------------------------------------------------------------------------
// Main persistent kernel (R14): 512 threads = 4 independent 128-thread groups.
// Group tile = 32 rows; warp nq covers cols nq*32, full m32 (2 x m16).
// ---------------------------------------------------------------------------
__global__ __launch_bounds__(512, 1)
void main_kernel(const int*   __restrict__ route_idx,
                 const int*   __restrict__ time_idx,
                 const uint4* __restrict__ RTB,
                 const uint4* __restrict__ TTB,
                 const float* __restrict__ w,
                 const float* __restrict__ fc_w,
                 const float* __restrict__ fc_b,
                 const float* __restrict__ mode_bias,
                 const float* __restrict__ ra_tab,
                 const float* __restrict__ tb_tab,
                 float*       __restrict__ out,
                 int batch, int ntiles)
{
    extern __shared__ uint32_t smu[];
    uint32_t* wp  = smu + WP_W;
    float*    fcs = reinterpret_cast<float*>(smu + FCS_W);
    float*    fci = reinterpret_cast<float*>(smu + FCI_W);
    float*    bia = reinterpret_cast<float*>(smu + BIA_W);

    const int tid  = threadIdx.x;
    const int gid  = tid >> 7;            // group 0..3
    const int lt   = tid & 127;
    const int lw   = lt >> 5;             // warp in group 0..3 (= nq)
    const int lane = tid & 31;
    const uint32_t sm_u32 = smem_u32(smu);

    // stage w bf16-pairs (all 512 threads)
    for (int i = tid; i < 128 * 128; i += 512) {
        const int n = i & 127, kp = i >> 7;
        const float f0 = (n < KOUT) ? __ldg(w + (2 * kp)     * KOUT + n) : 0.f;
        const float f1 = (n < KOUT) ? __ldg(w + (2 * kp + 1) * KOUT + n) : 0.f;
        wp[n * XSTR + kp] = pack_bf16(f0, f1);
    }
    if (tid < 128)                 fcs[tid] = (tid < KOUT) ? __ldg(fc_w + tid) : 0.f;
    if (tid >= 128 && tid < 153)   fci[tid - 128] = __ldg(fc_w + KOUT + tid - 128);
    if (tid >= 160 && tid < 185)   bia[tid - 160] = __ldg(mode_bias + tid - 160);
    if (tid < 256)                 reinterpret_cast<float*>(smu + OAC_W)[tid] = 0.f;

    const float fcb = __ldg(fc_b);

    float*    oacg = reinterpret_cast<float*>(smu + OAC_W) + gid * 64;
    uint32_t* xg   = smu + XB_W + gid * (2 * 32 * XSTR);
    float*    rv5g = reinterpret_cast<float*>(smu + RV5_W) + gid * (3 * 32 * CDIM);
    float*    tv5g = reinterpret_cast<float*>(smu + TV5_W) + gid * (3 * 32 * CDIM);

    const int nq = lw;                    // n-quarter
    const int t  = lane & 3;
    const int barid = 1 + gid;

    // ldmatrix addressing
    const int a_row = (lane & 7) + ((lane >> 3) & 1) * 8;
    const int a_kq  = (lane >> 4) * 4;
    const int b_n   = ((lane >> 4) << 3) + (lane & 7);
    const int b_kq  = ((lane >> 3) & 1) * 4;
    uint32_t bAddr[2];
#pragma unroll
    for (int p = 0; p < 2; p++)
        bAddr[p] = sm_u32 + (WP_W + (nq * 32 + p * 16 + b_n) * XSTR + b_kq) * 4;

    const int step  = gridDim.x * 4;
    const int first = blockIdx.x * 4 + gid;
    const int li    = lane & 7;

    __syncthreads();   // staging visible to all groups

    // ---- prologue: gather first tile -> x slot 0, rv5 slot 0 ----
    {
        const int ei = min(first * 32 + lw * 8 + li, batch - 1);
        const int ridx = __ldg(route_idx + ei);
        const int tidx = __ldg(time_idx  + ei);
        if (lane < 8) {
#pragma unroll
            for (int c = 0; c < CDIM; c++) {
                rv5g[(lw * 8 + li) * CDIM + c] = __ldg(ra_tab + (size_t)ridx * CDIM + c);
                tv5g[(lw * 8 + li) * CDIM + c] = __ldg(tb_tab + (size_t)tidx * CDIM + c);
            }
        }
#pragma unroll
        for (int h = 0; h < 2; h++) {
            uint4 rr[4], tt[4];
#pragma unroll
            for (int i = 0; i < 4; i++) {
                const int r0 = __shfl_sync(0xffffffffu, ridx, h * 4 + i);
                const int t0 = __shfl_sync(0xffffffffu, tidx, h * 4 + i);
                rr[i] = __ldg(RTB + (size_t)r0 * 32 + lane);
                tt[i] = __ldg(TTB + (size_t)t0 * 32 + lane);
            }
#pragma unroll
            for (int i = 0; i < 4; i++)
                *reinterpret_cast<uint4*>(xg + (lw * 8 + h * 4 + i) * XSTR + 4 * lane)
                    = hmul8(rr[i], tt[i]);
        }
    }
    BARG(barid);

    int it = 0;
    for (int tile = first; tile < ntiles; tile += step, it++) {
        const int s   = it & 1;
        const int rs  = it % 3;
        const int rsn = (it + 1) % 3;
        uint32_t* xb_cur = xg + s * (32 * XSTR);
        uint32_t* xb_nxt = xg + (s ^ 1) * (32 * XSTR);
        const bool have_next = (tile + step < ntiles);

        int nridx = 0, ntidx = 0;
        uint4 rr[4], tt[4];

        // ---- issue next-tile idx + rows 0-3 + rv5 prefetch (slot rsn) ----
        if (have_next) {
            const int ei = min((tile + step) * 32 + lw * 8 + li, batch - 1);
            nridx = __ldg(route_idx + ei);
            ntidx = __ldg(time_idx  + ei);
#pragma unroll
            for (int i = 0; i < 4; i++) {
                const int r0 = __shfl_sync(0xffffffffu, nridx, i);
                const int t0 = __shfl_sync(0xffffffffu, ntidx, i);
                rr[i] = __ldg(RTB + (size_t)r0 * 32 + lane);
                tt[i] = __ldg(TTB + (size_t)t0 * 32 + lane);
            }
            if (lane < 8) {
#pragma unroll
                for (int c = 0; c < CDIM; c++) {
                    rv5g[(rsn * 32 + lw * 8 + li) * CDIM + c] = __ldg(ra_tab + (size_t)nridx * CDIM + c);
                    tv5g[(rsn * 32 + lw * 8 + li) * CDIM + c] = __ldg(tb_tab + (size_t)ntidx * CDIM + c);
                }
            }
        }

        // ---- mma over K: 16 chunks of k16 ----
        float acc[2][4][4];
#pragma unroll
        for (int m = 0; m < 2; m++)
#pragma unroll
            for (int n = 0; n < 4; n++)
#pragma unroll
                for (int q = 0; q < 4; q++) acc[m][n][q] = 0.f;

        uint32_t aAddr[2];
#pragma unroll
        for (int m = 0; m < 2; m++)
            aAddr[m] = sm_u32 + (uint32_t)((xb_cur - smu)
                       + (m * 16 + a_row) * XSTR + a_kq) * 4;

        // ---- MMA kc 0-7 (hides next-tile LDG latency) ----
#pragma unroll 2
        for (int kc = 0; kc < 8; kc++) {
            const uint32_t kb = kc * 32;
            uint32_t bb[8];
            LDSM_X4(bb[0], bb[1], bb[2], bb[3], bAddr[0] + kb);
            LDSM_X4(bb[4], bb[5], bb[6], bb[7], bAddr[1] + kb);
#pragma unroll
            for (int m = 0; m < 2; m++) {
                uint32_t a[4];
                LDSM_X4(a[0], a[1], a[2], a[3], aAddr[m] + kb);
                mma_bf16(acc[m][0], a, bb[0], bb[1]);
                mma_bf16(acc[m][1], a, bb[2], bb[3]);
                mma_bf16(acc[m][2], a, bb[4], bb[5]);
                mma_bf16(acc[m][3], a, bb[6], bb[7]);
            }
        }

        // ---- commit rows 0-3; issue rows 4-7 ----
        if (have_next) {
#pragma unroll
            for (int i = 0; i < 4; i++)
                *reinterpret_cast<uint4*>(xb_nxt + (lw * 8 + i) * XSTR + 4 * lane)
                    = hmul8(rr[i], tt[i]);
#pragma unroll
            for (int i = 0; i < 4; i++) {
                const int r0 = __shfl_sync(0xffffffffu, nridx, 4 + i);
                const int t0 = __shfl_sync(0xffffffffu, ntidx, 4 + i);
                rr[i] = __ldg(RTB + (size_t)r0 * 32 + lane);
                tt[i] = __ldg(TTB + (size_t)t0 * 32 + lane);
            }
        }

        // ---- MMA kc 8-15 ----
#pragma unroll 2
        for (int kc = 8; kc < 16; kc++) {
            const uint32_t kb = kc * 32;
            uint32_t bb[8];
            LDSM_X4(bb[0], bb[1], bb[2], bb[3], bAddr[0] + kb);
            LDSM_X4(bb[4], bb[5], bb[6], bb[7], bAddr[1] + kb);
#pragma unroll
            for (int m = 0; m < 2; m++) {
                uint32_t a[4];
                LDSM_X4(a[0], a[1], a[2], a[3], aAddr[m] + kb);
                mma_bf16(acc[m][0], a, bb[0], bb[1]);
                mma_bf16(acc[m][1], a, bb[2], bb[3]);
                mma_bf16(acc[m][2], a, bb[4], bb[5]);
                mma_bf16(acc[m][3], a, bb[6], bb[7]);
            }
        }

        // ---- commit rows 4-7 ----
        if (have_next) {
#pragma unroll
            for (int i = 0; i < 4; i++)
                *reinterpret_cast<uint4*>(xb_nxt + (lw * 8 + 4 + i) * XSTR + 4 * lane)
                    = hmul8(rr[i], tt[i]);
        }

        // ---- fold relu * fc_w -> per-row partials (oac slot s) ----
        float* oacs = oacg + s * 32;
#pragma unroll
        for (int m = 0; m < 2; m++) {
            float p0 = 0.f, p1 = 0.f;
#pragma unroll
            for (int n = 0; n < 4; n++) {
                const int col = nq * 32 + n * 8 + 2 * t;
                const float f0 = fcs[col], f1 = fcs[col + 1];
                p0 = fmaf(f0, fmaxf(acc[m][n][0], 0.f), p0);
                p0 = fmaf(f1, fmaxf(acc[m][n][1], 0.f), p0);
                p1 = fmaf(f0, fmaxf(acc[m][n][2], 0.f), p1);
                p1 = fmaf(f1, fmaxf(acc[m][n][3], 0.f), p1);
            }
            p0 += __shfl_xor_sync(0xffffffffu, p0, 1);
            p0 += __shfl_xor_sync(0xffffffffu, p0, 2);
            p1 += __shfl_xor_sync(0xffffffffu, p1, 1);
            p1 += __shfl_xor_sync(0xffffffffu, p1, 2);
            if (t == 0) {
                const int row = m * 16 + (lane >> 2);
                atomicAdd(oacs + row, p0);
                atomicAdd(oacs + row + 8, p1);
            }
        }
        BARG(barid);   // single barrier: partials + slot^1 x-stores + rv5[rsn] complete

        // ---- epilogue: 4 threads/row over 32 rows ----
        {
            const int row = lt >> 2;
            const int p   = lt & 3;
            const int eo  = tile * 32 + row;
            const float* rv = rv5g + (rs * 32 + row) * CDIM;
            const float* tv = tv5g + (rs * 32 + row) * CDIM;
            const int start = p ? (1 + p * 6) : 0;
            const int cnt   = p ? 6 : 7;
            float val = 0.f;
#pragma unroll
            for (int k = 0; k < 7; k++) {
                if (k < cnt) {
                    const int idx = start + k;
                    const int i5  = idx / 5, j5 = idx - 5 * i5;
                    const float x  = fmaf(rv[i5], tv[j5], bia[idx]);
                    const float sg = 1.0f / (1.0f + __expf(-x));
                    val = fmaf(fci[idx], sg, val);
                }
            }
            val += __shfl_xor_sync(0xffffffffu, val, 1);
            val += __shfl_xor_sync(0xffffffffu, val, 2);
            if (p == 0) {
                if (eo < batch) out[eo] = fcb + oacs[row] + val;
                oacs[row] = 0.f;
            }
        }
        // next iter uses x slot s^1 / oac slot s^1 / rv5 slot rsn;
        // slot-s reuse is fenced by the next iteration's BARG.
    }
}

// ---------------------------------------------------------------------------
extern "C" void kernel_launch(void* const* d_in, const int* in_sizes, int n_in,
                              void* d_out, int out_size)
{
    const int*   route_idx   = (const int*)  d_in[0];
    const int*   time_idx    = (const int*)  d_in[1];
    const float* route_table = (const float*)d_in[2];
    const float* time_table  = (const float*)d_in[3];
    const float* w           = (const float*)d_in[4];
    const float* mode_a      = (const float*)d_in[5];
    const float* mode_b      = (const float*)d_in[6];
    const float* mode_bias   = (const float*)d_in[7];
    const float* fc_w        = (const float*)d_in[8];
    const float* fc_b        = (const float*)d_in[9];
    float*       out         = (float*)d_out;

    const int batch    = in_sizes[0];
    const int n_routes = in_sizes[2] / DIM;
    const int n_time   = in_sizes[3] / DIM;

    float *ra_ptr = nullptr, *tb_ptr = nullptr;
    __nv_bfloat16 *rtb_ptr = nullptr, *ttb_ptr = nullptr;
    cudaGetSymbolAddress((void**)&ra_ptr,  g_ra);
    cudaGetSymbolAddress((void**)&tb_ptr,  g_tb);
    cudaGetSymbolAddress((void**)&rtb_ptr, g_rtb);
    cudaGetSymbolAddress((void**)&ttb_ptr, g_ttb);

    {
        const int total = n_routes + n_time;
        proj_conv<<<(total + 63) / 64, 512>>>(route_table, time_table, mode_a, mode_b,
                                              ra_ptr, tb_ptr, rtb_ptr, ttb_ptr,
                                              n_routes, n_time);
    }

    const int ntiles = (batch + 31) / 32;
    const int smem_bytes = SM_WORDS * 4;   // 219904
    cudaFuncSetAttribute(main_kernel, cudaFuncAttributeMaxDynamicSharedMemorySize, smem_bytes);

    int grid = 148;
    main_kernel<<<grid, 512, smem_bytes>>>(route_idx, time_idx,
                                           (const uint4*)rtb_ptr, (const uint4*)ttb_ptr,
                                           w, fc_w, fc_b, mode_bias,
                                           ra_ptr, tb_ptr, out, batch, ntiles);
}